// round 12
// baseline (speedup 1.0000x reference)
#include <cuda_runtime.h>
#include <cstdint>

// Dynamic local filtering: out[n,c,h,w] = sum_{k1,k2} x_pad[n,c,h+k1,w+k2] * kern[n,(c*25+k1*5+k2),h,w]
// then leaky_relu(0.2). Replicate padding. Shapes fixed: N=4, C=8, H=W=256, K=5.
// R9: TMA-class bulk weight streaming. Each CTA's 25 tap-blocks (4KB contiguous
//     each) are fetched with cp.async.bulk into a 100KB smem buffer against two
//     mbarriers (13/12 taps); warps consume from smem. Request generation is
//     hardware-paced and strictly sequential -> no L1tex queue, no reg pressure.

#define WID 256
#define HEI 256
#define HW  (WID * HEI)
#define TW  256   // full width
#define TH  4     // rows per CTA
#define SW  (TW + 4)   // 260
#define SH  (TH + 4)   // 8

#define WTS_BYTES   (25 * TH * WID * 4)          // 102400
#define TILE_OFF    WTS_BYTES                    // 102400
#define TILE_BYTES  (SH * SW * 4)                // 8320
#define MBAR_OFF    (TILE_OFF + TILE_BYTES)      // 110720 (16B aligned)
#define SMEM_TOTAL  (MBAR_OFF + 16)

__device__ __forceinline__ uint32_t smem_u32(const void* p) {
    uint32_t a;
    asm("{ .reg .u64 t; cvta.to.shared.u64 t, %1; cvt.u32.u64 %0, t; }"
        : "=r"(a) : "l"(p));
    return a;
}

__device__ __forceinline__ void mbar_init(uint32_t mbar, uint32_t count) {
    asm volatile("mbarrier.init.shared.b64 [%0], %1;" :: "r"(mbar), "r"(count) : "memory");
}

__device__ __forceinline__ void mbar_expect_tx(uint32_t mbar, uint32_t bytes) {
    asm volatile("mbarrier.arrive.expect_tx.shared.b64 _, [%0], %1;"
                 :: "r"(mbar), "r"(bytes) : "memory");
}

__device__ __forceinline__ void bulk_copy(uint32_t dst_smem, const void* src, uint32_t bytes, uint32_t mbar) {
    asm volatile(
        "cp.async.bulk.shared::cta.global.mbarrier::complete_tx::bytes [%0], [%1], %2, [%3];"
        :: "r"(dst_smem), "l"(src), "r"(bytes), "r"(mbar) : "memory");
}

__device__ __forceinline__ void mbar_wait(uint32_t mbar, uint32_t parity) {
    asm volatile(
        "{\n\t"
        ".reg .pred P;\n\t"
        "WAIT_%=:\n\t"
        "mbarrier.try_wait.parity.acquire.cta.shared::cta.b64 P, [%0], %1;\n\t"
        "@!P bra WAIT_%=;\n\t"
        "}"
        :: "r"(mbar), "r"(parity) : "memory");
}

__global__ __launch_bounds__(256)
void dynconv5x5_kernel(const float* __restrict__ x,
                       const float* __restrict__ kern,
                       float* __restrict__ out)
{
    extern __shared__ __align__(128) char smem_raw[];
    float* wts  = (float*)smem_raw;                       // 25 blocks of [TH][WID]
    float* tile = (float*)(smem_raw + TILE_OFF);
    const uint32_t mbarA = smem_u32(smem_raw + MBAR_OFF);
    const uint32_t mbarB = mbarA + 8;

    const int plane = blockIdx.z;           // n*C + c, 0..31
    const int by = blockIdx.y * TH;
    const int tid = threadIdx.x;            // 0..255

    if (tid == 0) {
        mbar_init(mbarA, 1);
        mbar_init(mbarB, 1);
    }
    __syncthreads();

    // ---- Enqueue all 25 bulk copies (4KB each, strictly contiguous) ----
    if (tid == 0) {
        const char* src_base = (const char*)kern
            + ((size_t)plane * 25 * HW + (size_t)by * WID) * 4;
        mbar_expect_tx(mbarA, 13 * TH * WID * 4);
        #pragma unroll
        for (int t = 0; t < 13; t++) {
            bulk_copy(smem_u32(wts + t * TH * WID),
                      src_base + (size_t)t * HW * 4,
                      TH * WID * 4, mbarA);
        }
        mbar_expect_tx(mbarB, 12 * TH * WID * 4);
        #pragma unroll
        for (int t = 13; t < 25; t++) {
            bulk_copy(smem_u32(wts + t * TH * WID),
                      src_base + (size_t)t * HW * 4,
                      TH * WID * 4, mbarB);
        }
    }

    // ---- x tile with replicate-clamped halo (L2 hits; overlaps bulk copies) ----
    const float* __restrict__ xp = x + (size_t)plane * HW;
    #pragma unroll
    for (int i = tid; i < SH * SW; i += 256) {
        int sy = i / SW;
        int sx = i - sy * SW;
        int gy = by + sy - 2; gy = max(0, min(HEI - 1, gy));
        int gx = sx - 2;      gx = max(0, min(WID - 1, gx));
        tile[i] = xp[gy * WID + gx];
    }
    __syncthreads();

    const int lx = tid & 63;                // 64 threads across the row
    const int ly = tid >> 6;                // 4 rows
    const int w0 = lx * 4;                  // first of 4 pixels handled
    const int h  = by + ly;

    // Stage the 8-wide x windows for all 5 dy rows (smem -> regs).
    float s[5][8];
    #pragma unroll
    for (int dy = 0; dy < 5; dy++) {
        const float4* srow = (const float4*)&tile[(ly + dy) * SW + w0];
        float4 s0 = srow[0];
        float4 s1 = srow[1];
        s[dy][0] = s0.x; s[dy][1] = s0.y; s[dy][2] = s0.z; s[dy][3] = s0.w;
        s[dy][4] = s1.x; s[dy][5] = s1.y; s[dy][6] = s1.z; s[dy][7] = s1.w;
    }

    float ax = 0.f, ay = 0.f, az = 0.f, aw = 0.f;
    const float4* w4 = (const float4*)wts;  // [t][ly][lx] -> t*256 + ly*64 + lx
    const int widx = ly * 64 + lx;

    // ---- Consume taps 0..12 once batch A lands ----
    mbar_wait(mbarA, 0);
    #pragma unroll
    for (int t = 0; t < 13; t++) {
        int dy = t / 5, dx = t % 5;
        float4 w = w4[t * 256 + widx];
        ax += w.x * s[dy][dx + 0];
        ay += w.y * s[dy][dx + 1];
        az += w.z * s[dy][dx + 2];
        aw += w.w * s[dy][dx + 3];
    }

    // ---- Consume taps 13..24 once batch B lands ----
    mbar_wait(mbarB, 0);
    #pragma unroll
    for (int t = 13; t < 25; t++) {
        int dy = t / 5, dx = t % 5;
        float4 w = w4[t * 256 + widx];
        ax += w.x * s[dy][dx + 0];
        ay += w.y * s[dy][dx + 1];
        az += w.z * s[dy][dx + 2];
        aw += w.w * s[dy][dx + 3];
    }

    // leaky_relu(0.2)
    ax = ax >= 0.f ? ax : 0.2f * ax;
    ay = ay >= 0.f ? ay : 0.2f * ay;
    az = az >= 0.f ? az : 0.2f * az;
    aw = aw >= 0.f ? aw : 0.2f * aw;

    float4 r = make_float4(ax, ay, az, aw);
    __stcs(&((float4*)out)[(size_t)plane * (HW / 4) + (size_t)(h * WID + w0) / 4], r);
}

extern "C" void kernel_launch(void* const* d_in, const int* in_sizes, int n_in,
                              void* d_out, int out_size)
{
    const float* x    = (const float*)d_in[0];   // (4, 8, 256, 256)
    const float* kern = (const float*)d_in[1];   // (4, 200, 256, 256)
    float* out = (float*)d_out;                  // (4, 8, 256, 256)

    static bool attr_set = false;
    if (!attr_set) {
        cudaFuncSetAttribute(dynconv5x5_kernel,
                             cudaFuncAttributeMaxDynamicSharedMemorySize, SMEM_TOTAL);
        attr_set = true;
    }

    dim3 block(256, 1, 1);
    dim3 grid(1, HEI / TH, 32);                  // (1, 64, 32) = 2048 CTAs
    dynconv5x5_kernel<<<grid, block, SMEM_TOTAL>>>(x, kern, out);
}

// round 15
// speedup vs baseline: 1.0557x; 1.0557x over previous
#include <cuda_runtime.h>

// Dynamic local filtering: out[n,c,h,w] = sum_{k1,k2} x_pad[n,c,h+k1,w+k2] * kern[n,(c*25+k1*5+k2),h,w]
// then leaky_relu(0.2). Replicate padding. Shapes fixed: N=4, C=8, H=W=256, K=5.
// R10 (re-bench after infra failure): full-width 256x8 tiles with 512-thread
//      CTAs so each tap-stream is one contiguous 8KB block per CTA. 4px/thread
//      LDG.128, split 13/12 pipelined weight preload, streaming cache hints.

#define WID 256
#define HEI 256
#define HW  (WID * HEI)
#define TW  256   // full width: 64 threads x 4 px per row
#define TH  8     // rows per CTA
#define SW  (TW + 4)   // 260 floats per smem row (float4-aligned)
#define SH  (TH + 4)   // 12

__global__ __launch_bounds__(512)
void dynconv5x5_kernel(const float* __restrict__ x,
                       const float* __restrict__ kern,
                       float* __restrict__ out)
{
    __shared__ float tile[SH * SW];

    const int plane = blockIdx.z;           // n*C + c, 0..31
    const int by = blockIdx.y * TH;
    const int tid = threadIdx.x;            // 0..511

    const int lx = tid & 63;                // 64 threads across the row
    const int ly = tid >> 6;                // 8 rows
    const int w0 = lx * 4;                  // first of 4 pixels handled
    const int h  = by + ly;

    // Weight pointer: per tap t, this thread's 4 pixels' weights are one float4.
    const float4* __restrict__ k4 = (const float4*)kern
        + (size_t)plane * 25 * (HW / 4)
        + (size_t)(h * WID + w0) / 4;

    // ---- First half of the weight preload: taps 0..12 (13 LDG.128 in flight) ----
    float4 kv[13];
    #pragma unroll
    for (int t = 0; t < 13; t++) {
        kv[t] = __ldcs(&k4[(size_t)t * (HW / 4)]);
    }

    // Cooperative load of x tile with halo; replicate padding via clamp.
    // (Overlaps with the in-flight weight loads; halo re-reads are L2 hits.)
    const float* __restrict__ xp = x + (size_t)plane * HW;
    #pragma unroll
    for (int i = tid; i < SH * SW; i += 512) {
        int sy = i / SW;
        int sx = i - sy * SW;
        int gy = by + sy - 2; gy = max(0, min(HEI - 1, gy));
        int gx = sx - 2;      gx = max(0, min(WID - 1, gx));
        tile[i] = xp[gy * WID + gx];
    }
    __syncthreads();

    float ax = 0.f, ay = 0.f, az = 0.f, aw = 0.f;

    // Stage the 8-wide x windows for all 5 dy rows once (smem -> regs).
    float s[5][8];
    #pragma unroll
    for (int dy = 0; dy < 5; dy++) {
        const float4* srow = (const float4*)&tile[(ly + dy) * SW + w0];
        float4 s0 = srow[0];
        float4 s1 = srow[1];
        s[dy][0] = s0.x; s[dy][1] = s0.y; s[dy][2] = s0.z; s[dy][3] = s0.w;
        s[dy][4] = s1.x; s[dy][5] = s1.y; s[dy][6] = s1.z; s[dy][7] = s1.w;
    }

    // ---- Consume taps 0..12 while issuing taps 13..24 ----
    // Barrier keeps ptxas from hoisting the second batch above the first
    // batch's consumption (which would recreate the 25-deep front burst).
    asm volatile("" ::: "memory");

    float4 kv2[12];
    #pragma unroll
    for (int t = 0; t < 12; t++) {
        kv2[t] = __ldcs(&k4[(size_t)(t + 13) * (HW / 4)]);
    }

    #pragma unroll
    for (int t = 0; t < 13; t++) {
        int dy = t / 5, dx = t % 5;
        float4 w = kv[t];
        ax += w.x * s[dy][dx + 0];
        ay += w.y * s[dy][dx + 1];
        az += w.z * s[dy][dx + 2];
        aw += w.w * s[dy][dx + 3];
    }

    #pragma unroll
    for (int t = 13; t < 25; t++) {
        int dy = t / 5, dx = t % 5;
        float4 w = kv2[t - 13];
        ax += w.x * s[dy][dx + 0];
        ay += w.y * s[dy][dx + 1];
        az += w.z * s[dy][dx + 2];
        aw += w.w * s[dy][dx + 3];
    }

    // leaky_relu(0.2)
    ax = ax >= 0.f ? ax : 0.2f * ax;
    ay = ay >= 0.f ? ay : 0.2f * ay;
    az = az >= 0.f ? az : 0.2f * az;
    aw = aw >= 0.f ? aw : 0.2f * aw;

    float4 r = make_float4(ax, ay, az, aw);
    __stcs(&((float4*)out)[(size_t)plane * (HW / 4) + (size_t)(h * WID + w0) / 4], r);
}

extern "C" void kernel_launch(void* const* d_in, const int* in_sizes, int n_in,
                              void* d_out, int out_size)
{
    const float* x    = (const float*)d_in[0];   // (4, 8, 256, 256)
    const float* kern = (const float*)d_in[1];   // (4, 200, 256, 256)
    float* out = (float*)d_out;                  // (4, 8, 256, 256)

    dim3 block(512, 1, 1);
    dim3 grid(1, HEI / TH, 32);                  // (1, 32, 32) = 1024 CTAs
    dynconv5x5_kernel<<<grid, block>>>(x, kern, out);
}